// round 6
// baseline (speedup 1.0000x reference)
#include <cuda_runtime.h>

// Reference semantics after dead-code elimination:
//   r  = eye(3)                       (unconditional overwrite in reference)
//   tb = -mean(mkpts0, axis=1)        ( = -r @ src_mean with r = I )
// Output: 12 floats = [r row-major (9), tb (3)].
//
// Inputs (metadata order): mkpts0 [3,8192] f32, mkpts1 [3,8192] f32 (unused),
// valid_scores [8192,8192] f32 (unused).
//
// Locked configuration (best measured across R1-R4 sweeps):
//   grid=3 (one CTA per row: spreads LDG issue across 3 SMs' LSUs),
//   TPB=1024 (2 fully-unrolled float4 loads/thread -> one DRAM round trip),
//   5-shfl warp reduce + 1 bar + 5-shfl fold.
// Kernel is at the launch-overhead floor: 96 KB read ~= 4 ns of HBM time;
// measured 3.84 us is T_ovh ramp + 1 DRAM round trip + reduction tail.

#define ROWLEN   8192
#define TPB      1024
#define NWARPS   (TPB / 32)          // 32
#define INV_NEG  (-1.0f / 8192.0f)   // exact: power-of-two divisor

__global__ void __launch_bounds__(TPB, 1)
svdhead_kernel(const float* __restrict__ mkpts0, float* __restrict__ out) {
    const int b = blockIdx.x;       // row 0..2
    const int t = threadIdx.x;

    // Block 0 writes the 3x3 identity (row-major, indices 0..8).
    if (b == 0 && t < 9) {
        out[t] = ((t & 3) == 0) ? 1.0f : 0.0f;   // t = 0,4,8 -> 1
    }

    // 8192 floats = 2048 float4; 1024 threads -> exactly 2 float4 each,
    // both issued back-to-back (one DRAM round trip, 2048 loads in flight
    // block-wide).
    const float4* row4 = reinterpret_cast<const float4*>(mkpts0) + (size_t)b * (ROWLEN / 4);
    float4 v0 = row4[t];
    float4 v1 = row4[t + TPB];

    float sum = ((v0.x + v0.y) + (v0.z + v0.w)) + ((v1.x + v1.y) + (v1.z + v1.w));

    // Warp tree reduce: 5 shfl.
    #pragma unroll
    for (int off = 16; off > 0; off >>= 1)
        sum += __shfl_xor_sync(0xFFFFFFFFu, sum, off);

    __shared__ float warp_sums[NWARPS];
    if ((t & 31) == 0) warp_sums[t >> 5] = sum;
    __syncthreads();

    // Single warp folds the 32 warp sums: 1 LDS + 5 shfl + 1 STG.
    if (t < 32) {
        float s = warp_sums[t];
        #pragma unroll
        for (int off = 16; off > 0; off >>= 1)
            s += __shfl_xor_sync(0xFFFFFFFFu, s, off);
        if (t == 0)
            out[9 + b] = s * INV_NEG;
    }
}

extern "C" void kernel_launch(void* const* d_in, const int* in_sizes, int n_in,
                              void* d_out, int out_size) {
    const float* mkpts0 = (const float*)d_in[0];
    float* out = (float*)d_out;
    svdhead_kernel<<<3, TPB>>>(mkpts0, out);
}

// round 8
// speedup vs baseline: 1.5035x; 1.5035x over previous
#include <cuda_runtime.h>

// Reference semantics after dead-code elimination:
//   r  = eye(3)                       (unconditional overwrite in reference)
//   tb = -mean(mkpts0, axis=1)        ( = -r @ src_mean with r = I )
// Output: 12 floats = [r row-major (9), tb (3)].
//
// Inputs (metadata order): mkpts0 [3,8192] f32, mkpts1 [3,8192] f32 (unused),
// valid_scores [8192,8192] f32 (unused).
//
// Locked shape (best measured): grid=3, TPB=1024, 2 float4 loads/thread.
// Tail this round: final fold via LDS.128 (8 lanes x float4) + 3 FADD +
// 3 SHFL instead of 1 LDS + 5 SHFL. (redux.f32 is NOT supported on sm_103.)

#define ROWLEN   8192
#define TPB      1024
#define NWARPS   (TPB / 32)          // 32
#define INV_NEG  (-1.0f / 8192.0f)   // exact: power-of-two divisor

__global__ void __launch_bounds__(TPB, 1)
svdhead_kernel(const float* __restrict__ mkpts0, float* __restrict__ out) {
    const int b = blockIdx.x;       // row 0..2
    const int t = threadIdx.x;

    // Block 0 writes the 3x3 identity (row-major, indices 0..8).
    if (b == 0 && t < 9) {
        out[t] = ((t & 3) == 0) ? 1.0f : 0.0f;   // t = 0,4,8 -> 1
    }

    // 8192 floats = 2048 float4; 1024 threads -> exactly 2 float4 each,
    // both issued back-to-back (one memory round trip block-wide).
    const float4* row4 = reinterpret_cast<const float4*>(mkpts0) + (size_t)b * (ROWLEN / 4);
    float4 v0 = row4[t];
    float4 v1 = row4[t + TPB];

    float sum = ((v0.x + v0.y) + (v0.z + v0.w)) + ((v1.x + v1.y) + (v1.z + v1.w));

    // Warp tree reduce: 5 shfl.
    #pragma unroll
    for (int off = 16; off > 0; off >>= 1)
        sum += __shfl_xor_sync(0xFFFFFFFFu, sum, off);

    __shared__ float warp_sums[NWARPS];
    if ((t & 31) == 0) warp_sums[t >> 5] = sum;
    __syncthreads();

    // Final fold: lanes 0-7 each grab 4 contiguous warp sums with one
    // conflict-free LDS.128, pairwise-add (fma pipe, cheap), then a 3-deep
    // shfl tree across the 8 lanes. Tail = LDS.128 + 3 FADD + 3 SHFL.
    if (t < 8) {
        float4 w = reinterpret_cast<const float4*>(warp_sums)[t];
        float s = (w.x + w.y) + (w.z + w.w);
        #pragma unroll
        for (int off = 4; off > 0; off >>= 1)
            s += __shfl_xor_sync(0x000000FFu, s, off);
        if (t == 0)
            out[9 + b] = s * INV_NEG;
    }
}

extern "C" void kernel_launch(void* const* d_in, const int* in_sizes, int n_in,
                              void* d_out, int out_size) {
    const float* mkpts0 = (const float*)d_in[0];
    float* out = (float*)d_out;
    svdhead_kernel<<<3, TPB>>>(mkpts0, out);
}